// round 7
// baseline (speedup 1.0000x reference)
#include <cuda_runtime.h>
#include <cuda_bf16.h>
#include <cstdint>
#include <math.h>

// Problem dims (fixed)
#define BB 1024
#define TT 64
#define N4H 2048
#define KBIG 1536   // 3*512 split-K
#define KHL  1024   // hi|lo storage per row
#define NCHUNK 24
#define STAGES 3
#define STAGE_BYTES 32768   // 16KB A + 16KB B

// ---------------- device scratch ----------------
__device__ float g_zx[134217728];                  // [65536, 2048] X@W + bias (gate-interleaved cols)
__device__ float g_c[524288];                      // [1024, 512]
__device__ float g_biasp[2048];                    // permuted bias
__device__ __nv_bfloat16 g_xhl[67108864];          // [65536, 1024] hi|lo of X
__device__ __nv_bfloat16 g_wb[3145728];            // [2048, 1536]  W^T split (rows permuted)
__device__ __nv_bfloat16 g_ub[3145728];            // [2048, 1536]  U^T split (rows permuted)
__device__ __nv_bfloat16 g_hhl[2097152];           // 2 x [1024, 1024] hi|lo of h (double buffer)

// ---------------- helpers ----------------
#define SW128(x) ((x) ^ (((x) >> 3) & 0x70))

__device__ __forceinline__ uint32_t smem_u32(const void* p) {
    uint32_t a;
    asm("{ .reg .u64 t; cvta.to.shared.u64 t, %1; cvt.u32.u64 %0, t; }" : "=r"(a) : "l"(p));
    return a;
}
__device__ __forceinline__ void cp_async16(uint32_t dst, const void* src) {
    asm volatile("cp.async.cg.shared.global [%0], [%1], 16;" :: "r"(dst), "l"(src));
}
#define CP_COMMIT() asm volatile("cp.async.commit_group;" ::: "memory")
#define CP_WAIT2()  asm volatile("cp.async.wait_group 2;" ::: "memory")
#define CP_WAIT1()  asm volatile("cp.async.wait_group 1;" ::: "memory")
#define CP_WAIT0()  asm volatile("cp.async.wait_group 0;" ::: "memory")

__device__ __forceinline__ void ldsm_x4(uint32_t& r0, uint32_t& r1, uint32_t& r2, uint32_t& r3,
                                        uint32_t addr) {
    asm volatile("ldmatrix.sync.aligned.m8n8.x4.shared.b16 {%0,%1,%2,%3}, [%4];"
                 : "=r"(r0), "=r"(r1), "=r"(r2), "=r"(r3) : "r"(addr));
}
__device__ __forceinline__ void mma_bf16(float* c, const uint32_t* a, const uint32_t* b) {
    asm volatile(
        "mma.sync.aligned.m16n8k16.row.col.f32.bf16.bf16.f32 "
        "{%0,%1,%2,%3}, {%4,%5,%6,%7}, {%8,%9}, {%0,%1,%2,%3};"
        : "+f"(c[0]), "+f"(c[1]), "+f"(c[2]), "+f"(c[3])
        : "r"(a[0]), "r"(a[1]), "r"(a[2]), "r"(a[3]), "r"(b[0]), "r"(b[1]));
}

// fast, accurate-enough activations (MUFU-based, err ~1e-6)
__device__ __forceinline__ float sigf(float x) {
    return 1.0f / (1.0f + __expf(-x));
}
__device__ __forceinline__ float tanh_(float x) {
    float ax = fabsf(x);
    float e  = __expf(2.0f * ax);
    float r  = 1.0f - 2.0f / (e + 1.0f);
    return copysignf(r, x);
}

// ---------------- shared GEMM mainloop ----------------
// acc[mi][ni][4] = A_hl[bm:bm+128, :] @ Bt[bn:bn+128, :]^T  with K_eff = 1536.
// A_hl: [*, 1024] (hi | lo), Bt: [2048, 1536] (hi | lo | hi).
// A chunk mapping: 0-15 -> hi cols, 16-23 -> lo cols.
struct WarpId { int wm, wn, g, r; };

__device__ __forceinline__ void gemm_mainloop(
    const __nv_bfloat16* __restrict__ A,
    const __nv_bfloat16* __restrict__ Bt,
    uint32_t dbase, int bm, int bn, int tid,
    float acc[4][4][4])
{
    const int lane = tid & 31;
    const int wid  = tid >> 5;
    const int wm = (wid >> 2) * 64;
    const int wn = (wid & 3) * 32;
    const int g = lane >> 3;
    const int r = lane & 7;

    auto issue_load = [&](int stage, int c) {
        const int seg  = c >> 3;
        const int acol = ((seg == 2) ? 512 : 0) + (c & 7) * 64;
        const int bcol = c * 64;
        const uint32_t sA = dbase + stage * STAGE_BYTES;
        const uint32_t sB = sA + 16384;
        #pragma unroll
        for (int j = 0; j < 4; j++) {
            int i = tid + j * 256;
            int row = i >> 3, c16 = i & 7;
            cp_async16(sA + SW128((uint32_t)(row * 128 + c16 * 16)),
                       A + (size_t)(bm + row) * KHL + acol + c16 * 8);
        }
        #pragma unroll
        for (int j = 0; j < 4; j++) {
            int i = tid + j * 256;
            int row = i >> 3, c16 = i & 7;
            cp_async16(sB + SW128((uint32_t)(row * 128 + c16 * 16)),
                       Bt + (size_t)(bn + row) * KBIG + bcol + c16 * 8);
        }
    };

    issue_load(0, 0); CP_COMMIT();
    issue_load(1, 1); CP_COMMIT();
    issue_load(2, 2); CP_COMMIT();

    for (int c = 0; c < NCHUNK; c++) {
        if (c < NCHUNK - 2)      { CP_WAIT2(); }
        else if (c == NCHUNK - 2){ CP_WAIT1(); }
        else                     { CP_WAIT0(); }
        __syncthreads();

        const uint32_t sA = dbase + (c % STAGES) * STAGE_BYTES;
        const uint32_t sB = sA + 16384;

        #pragma unroll
        for (int kk = 0; kk < 4; kk++) {
            uint32_t af[4][4];
            #pragma unroll
            for (int mi = 0; mi < 4; mi++) {
                int row = wm + mi * 16 + (g & 1) * 8 + r;
                int col = kk * 16 + (g >> 1) * 8;
                ldsm_x4(af[mi][0], af[mi][1], af[mi][2], af[mi][3],
                        sA + SW128((uint32_t)(row * 128 + col * 2)));
            }
            uint32_t bf[4][2];
            #pragma unroll
            for (int half = 0; half < 2; half++) {
                int row = wn + half * 16 + (g >> 1) * 8 + r;
                int col = kk * 16 + (g & 1) * 8;
                ldsm_x4(bf[half * 2][0], bf[half * 2][1],
                        bf[half * 2 + 1][0], bf[half * 2 + 1][1],
                        sB + SW128((uint32_t)(row * 128 + col * 2)));
            }
            #pragma unroll
            for (int mi = 0; mi < 4; mi++)
                #pragma unroll
                for (int ni = 0; ni < 4; ni++)
                    mma_bf16(acc[mi][ni], af[mi], bf[ni]);
        }
        __syncthreads();
        if (c + 3 < NCHUNK) { issue_load(c % STAGES, c + 3); CP_COMMIT(); }
    }
}

// ---------------- phase-1 GEMM: zx = X@W + bias (permuted cols) ----------------
__global__ __launch_bounds__(256) void phase1_kernel(
    const __nv_bfloat16* __restrict__ A,
    const __nv_bfloat16* __restrict__ Bt,
    float* __restrict__ C)
{
    extern __shared__ char dyn[];
    uint32_t dbase = (smem_u32(dyn) + 1023u) & ~1023u;
    const int tid = threadIdx.x;
    const int bm = blockIdx.y * 128;
    const int bn = blockIdx.x * 128;

    float acc[4][4][4];
    #pragma unroll
    for (int i = 0; i < 4; i++)
        #pragma unroll
        for (int j = 0; j < 4; j++)
            #pragma unroll
            for (int k = 0; k < 4; k++)
                acc[i][j][k] = 0.0f;

    gemm_mainloop(A, Bt, dbase, bm, bn, tid, acc);

    const int lane = tid & 31;
    const int wid  = tid >> 5;
    const int wm = (wid >> 2) * 64;
    const int wn = (wid & 3) * 32;
    const int qrow = lane >> 2;
    const int qcol = (lane & 3) * 2;
    #pragma unroll
    for (int mi = 0; mi < 4; mi++) {
        #pragma unroll
        for (int ni = 0; ni < 4; ni++) {
            int row = bm + wm + mi * 16 + qrow;
            int col = bn + wn + ni * 8 + qcol;
            float b0 = g_biasp[col];
            float b1 = g_biasp[col + 1];
            float2 v0 = { acc[mi][ni][0] + b0, acc[mi][ni][1] + b1 };
            float2 v1 = { acc[mi][ni][2] + b0, acc[mi][ni][3] + b1 };
            *reinterpret_cast<float2*>(C + (size_t)row * N4H + col) = v0;
            *reinterpret_cast<float2*>(C + (size_t)(row + 8) * N4H + col) = v1;
        }
    }
}

// ---------------- fused recurrent step: z = h@U; LSTM update in epilogue ------
__global__ __launch_bounds__(256) void fused_step_kernel(
    int t,
    const __nv_bfloat16* __restrict__ hread,
    __nv_bfloat16* __restrict__ hwrite,
    float* __restrict__ out)
{
    extern __shared__ char dyn[];
    uint32_t dbase = (smem_u32(dyn) + 1023u) & ~1023u;
    const int tid = threadIdx.x;
    const int bm = blockIdx.y * 128;
    const int bn = blockIdx.x * 128;

    float acc[4][4][4];
    #pragma unroll
    for (int i = 0; i < 4; i++)
        #pragma unroll
        for (int j = 0; j < 4; j++)
            #pragma unroll
            for (int k = 0; k < 4; k++)
                acc[i][j][k] = 0.0f;

    gemm_mainloop(hread, g_ub, dbase, bm, bn, tid, acc);

    // LSTM epilogue: warp n-tile (32 cols) = 4 gates x 8 k-values.
    const int lane = tid & 31;
    const int wid  = tid >> 5;
    const int wm = (wid >> 2) * 64;
    const int wn = (wid & 3) * 32;
    const int qrow = lane >> 2;
    const int qcol = (lane & 3) * 2;
    const int blk = (bn + wn) >> 5;
    const int colbase = blk * 32 + qcol;   // permuted zx col of gate i
    const int kbase = blk * 8 + qcol;      // real k

    #pragma unroll
    for (int mi = 0; mi < 4; mi++) {
        #pragma unroll
        for (int rr = 0; rr < 2; rr++) {
            const int b = bm + wm + mi * 16 + qrow + rr * 8;
            const size_t zxoff = ((size_t)b * TT + t) * N4H + colbase;
            const float2 zi2 = *reinterpret_cast<const float2*>(g_zx + zxoff);
            const float2 zf2 = *reinterpret_cast<const float2*>(g_zx + zxoff + 8);
            const float2 zg2 = *reinterpret_cast<const float2*>(g_zx + zxoff + 16);
            const float2 zo2 = *reinterpret_cast<const float2*>(g_zx + zxoff + 24);
            const float2 cp2 = *reinterpret_cast<const float2*>(g_c + (size_t)b * 512 + kbase);

            float cn[2], hn[2];
            #pragma unroll
            for (int jj = 0; jj < 2; jj++) {
                const int ai = rr * 2 + jj;
                float zi = acc[mi][0][ai] + (jj ? zi2.y : zi2.x);
                float zf = acc[mi][1][ai] + (jj ? zf2.y : zf2.x);
                float zg = acc[mi][2][ai] + (jj ? zg2.y : zg2.x);
                float zo = acc[mi][3][ai] + (jj ? zo2.y : zo2.x);
                float i_ = sigf(zi);
                float f_ = sigf(zf);
                float g_ = tanh_(zg);
                float o_ = sigf(zo);
                float cpv = jj ? cp2.y : cp2.x;
                cn[jj] = f_ * cpv + i_ * g_;
                hn[jj] = o_ * tanh_(cn[jj]);
            }
            float2 co = { cn[0], cn[1] };
            float2 ho = { hn[0], hn[1] };
            *reinterpret_cast<float2*>(g_c + (size_t)b * 512 + kbase) = co;
            *reinterpret_cast<float2*>(out + ((size_t)b * TT + t) * 512 + kbase) = ho;

            __nv_bfloat16 hi0 = __float2bfloat16(hn[0]);
            __nv_bfloat16 hi1 = __float2bfloat16(hn[1]);
            float lo0 = hn[0] - __bfloat162float(hi0);
            float lo1 = hn[1] - __bfloat162float(hi1);
            __nv_bfloat162 hi2 = __halves2bfloat162(hi0, hi1);
            __nv_bfloat162 lo2 = __floats2bfloat162_rn(lo0, lo1);
            *reinterpret_cast<__nv_bfloat162*>(hwrite + (size_t)b * KHL + kbase) = hi2;
            *reinterpret_cast<__nv_bfloat162*>(hwrite + (size_t)b * KHL + 512 + kbase) = lo2;
        }
    }
}

// ---------------- conversion / init kernels ----------------
__global__ __launch_bounds__(256) void conv_x_kernel(const float* __restrict__ X) {
    int idx = blockIdx.x * 256 + threadIdx.x;          // over 65536*512
    int m = idx >> 9, k = idx & 511;
    float v = X[idx];
    __nv_bfloat16 hi = __float2bfloat16(v);
    g_xhl[(size_t)m * KHL + k] = hi;
    g_xhl[(size_t)m * KHL + 512 + k] = __float2bfloat16(v - __bfloat162float(hi));
}

__global__ __launch_bounds__(256) void conv_w_kernel(const float* __restrict__ W,
                                                     __nv_bfloat16* __restrict__ Bt) {
    int idx = blockIdx.x * 256 + threadIdx.x;          // over 512*2048, W[k][n]
    int k = idx >> 11, n = idx & 2047;
    int gate = n >> 9, kk = n & 511;
    int pn = ((kk >> 3) << 5) + (gate << 3) + (kk & 7);   // gate-interleaved row
    float v = W[idx];
    __nv_bfloat16 hi = __float2bfloat16(v);
    __nv_bfloat16 lo = __float2bfloat16(v - __bfloat162float(hi));
    Bt[(size_t)pn * KBIG + k] = hi;
    Bt[(size_t)pn * KBIG + 512 + k] = lo;
    Bt[(size_t)pn * KBIG + 1024 + k] = hi;
}

__global__ void bias_perm_kernel(const float* __restrict__ bias) {
    int n = blockIdx.x * 256 + threadIdx.x;
    if (n < 2048) {
        int gate = n >> 9, kk = n & 511;
        int pn = ((kk >> 3) << 5) + (gate << 3) + (kk & 7);
        g_biasp[pn] = bias[n];
    }
}

// t = 0 step: h=c=0, gates from zx only
__global__ __launch_bounds__(256) void step0_kernel(float* __restrict__ out,
                                                    __nv_bfloat16* __restrict__ hwrite) {
    int idx = blockIdx.x * 256 + threadIdx.x;          // 0..B*H-1
    int b = idx >> 9;
    int k = idx & 511;
    size_t base = ((size_t)b * TT) * N4H + ((k >> 3) << 5) + (k & 7);
    float zi = g_zx[base];
    float zf = g_zx[base + 8];
    float zg = g_zx[base + 16];
    float zo = g_zx[base + 24];
    (void)zf;
    float i_ = sigf(zi);
    float g_ = tanh_(zg);
    float o_ = sigf(zo);
    float cn = i_ * g_;
    float hn = o_ * tanh_(cn);
    g_c[idx] = cn;
    out[((size_t)b * TT) * 512 + k] = hn;
    __nv_bfloat16 hi = __float2bfloat16(hn);
    hwrite[(size_t)b * KHL + k] = hi;
    hwrite[(size_t)b * KHL + 512 + k] = __float2bfloat16(hn - __bfloat162float(hi));
}

// ---------------- launch ----------------
extern "C" void kernel_launch(void* const* d_in, const int* in_sizes, int n_in,
                              void* d_out, int out_size)
{
    const float* X    = (const float*)d_in[0];
    const float* W    = (const float*)d_in[1];
    const float* U    = (const float*)d_in[2];
    const float* bias = (const float*)d_in[3];
    float* out = (float*)d_out;

    float* zx_p;
    __nv_bfloat16 *xhl_p, *wb_p, *ub_p, *hhl_p;
    cudaGetSymbolAddress((void**)&zx_p,  g_zx);
    cudaGetSymbolAddress((void**)&xhl_p, g_xhl);
    cudaGetSymbolAddress((void**)&wb_p,  g_wb);
    cudaGetSymbolAddress((void**)&ub_p,  g_ub);
    cudaGetSymbolAddress((void**)&hhl_p, g_hhl);

    const int SMEM = STAGES * STAGE_BYTES + 1024;   // 99328
    cudaFuncSetAttribute(phase1_kernel,
                         cudaFuncAttributeMaxDynamicSharedMemorySize, SMEM);
    cudaFuncSetAttribute(fused_step_kernel,
                         cudaFuncAttributeMaxDynamicSharedMemorySize, SMEM);

    // conversions (with gate-interleaved column permutation for W/U/bias)
    conv_x_kernel<<<(65536 * 512) / 256, 256>>>(X);
    conv_w_kernel<<<(512 * 2048) / 256, 256>>>(W, wb_p);
    conv_w_kernel<<<(512 * 2048) / 256, 256>>>(U, ub_p);
    bias_perm_kernel<<<8, 256>>>(bias);

    // Phase 1: zx = X@W + bias  (M=65536, N=2048, permuted cols)
    phase1_kernel<<<dim3(N4H / 128, 65536 / 128), 256, SMEM>>>(xhl_p, wb_p, zx_p);

    // t = 0 (writes h buffer 0)
    step0_kernel<<<(BB * 512) / 256, 256>>>(out, hhl_p);

    // t = 1..63: fused GEMM + LSTM update, double-buffered h
    for (int t = 1; t < TT; t++) {
        const __nv_bfloat16* hread = hhl_p + ((t - 1) & 1) * 1048576;
        __nv_bfloat16* hwrite      = hhl_p + (t & 1) * 1048576;
        fused_step_kernel<<<dim3(N4H / 128, BB / 128), 256, SMEM>>>(t, hread, hwrite, out);
    }
}

// round 9
// speedup vs baseline: 1.0119x; 1.0119x over previous
#include <cuda_runtime.h>
#include <cuda_bf16.h>
#include <cstdint>
#include <math.h>

// Problem dims (fixed)
#define BB 1024
#define TT 64
#define N4H 2048
#define KBIG 1536   // 3*512 split-K
#define KHL  1024   // hi|lo storage per row
#define NCHUNK 24
#define STAGE_BYTES 32768   // 16KB A + 16KB B

// ---------------- device scratch ----------------
__device__ float g_zx[134217728];                  // [65536, 2048] X@W + bias (gate-interleaved cols)
__device__ float g_c[524288];                      // [1024, 512]
__device__ float g_biasp[2048];                    // permuted bias
__device__ __nv_bfloat16 g_xhl[67108864];          // [65536, 1024] hi|lo of X
__device__ __nv_bfloat16 g_wb[3145728];            // [2048, 1536]  W^T split (rows permuted)
__device__ __nv_bfloat16 g_ub[3145728];            // [2048, 1536]  U^T split (rows permuted)
__device__ __nv_bfloat16 g_hhl[2097152];           // 2 x [1024, 1024] hi|lo of h (double buffer)

// ---------------- helpers ----------------
#define SW128(x) ((x) ^ (((x) >> 3) & 0x70))

__device__ __forceinline__ uint32_t smem_u32(const void* p) {
    uint32_t a;
    asm("{ .reg .u64 t; cvta.to.shared.u64 t, %1; cvt.u32.u64 %0, t; }" : "=r"(a) : "l"(p));
    return a;
}
__device__ __forceinline__ void cp_async16(uint32_t dst, const void* src) {
    asm volatile("cp.async.cg.shared.global [%0], [%1], 16;" :: "r"(dst), "l"(src));
}
#define CP_COMMIT() asm volatile("cp.async.commit_group;" ::: "memory")
#define CP_WAIT1()  asm volatile("cp.async.wait_group 1;" ::: "memory")
#define CP_WAIT0()  asm volatile("cp.async.wait_group 0;" ::: "memory")

__device__ __forceinline__ void ldsm_x4(uint32_t& r0, uint32_t& r1, uint32_t& r2, uint32_t& r3,
                                        uint32_t addr) {
    asm volatile("ldmatrix.sync.aligned.m8n8.x4.shared.b16 {%0,%1,%2,%3}, [%4];"
                 : "=r"(r0), "=r"(r1), "=r"(r2), "=r"(r3) : "r"(addr));
}
__device__ __forceinline__ void mma_bf16(float* c, const uint32_t* a, const uint32_t* b) {
    asm volatile(
        "mma.sync.aligned.m16n8k16.row.col.f32.bf16.bf16.f32 "
        "{%0,%1,%2,%3}, {%4,%5,%6,%7}, {%8,%9}, {%0,%1,%2,%3};"
        : "+f"(c[0]), "+f"(c[1]), "+f"(c[2]), "+f"(c[3])
        : "r"(a[0]), "r"(a[1]), "r"(a[2]), "r"(a[3]), "r"(b[0]), "r"(b[1]));
}

// fast, accurate-enough activations (MUFU-based, err ~1e-6)
__device__ __forceinline__ float sigf(float x) {
    return 1.0f / (1.0f + __expf(-x));
}
__device__ __forceinline__ float tanh_(float x) {
    float ax = fabsf(x);
    float e  = __expf(2.0f * ax);
    float r  = 1.0f - 2.0f / (e + 1.0f);
    return copysignf(r, x);
}

// ---------------- shared GEMM mainloop (2-stage) ----------------
// acc[mi][ni][4] = A_hl[bm:bm+128, :] @ Bt[bn:bn+128, :]^T  with K_eff = 1536.
// A_hl: [*, 1024] (hi | lo), Bt: [2048, 1536] (hi | lo | hi).
// A chunk mapping: 0-15 -> hi cols, 16-23 -> lo cols.
__device__ __forceinline__ void gemm_mainloop(
    const __nv_bfloat16* __restrict__ A,
    const __nv_bfloat16* __restrict__ Bt,
    uint32_t dbase, int bm, int bn, int tid,
    float acc[4][4][4])
{
    const int lane = tid & 31;
    const int wid  = tid >> 5;
    const int wm = (wid >> 2) * 64;
    const int wn = (wid & 3) * 32;
    const int g = lane >> 3;
    const int r = lane & 7;

    auto issue_load = [&](int stage, int c) {
        const int seg  = c >> 3;
        const int acol = ((seg == 2) ? 512 : 0) + (c & 7) * 64;
        const int bcol = c * 64;
        const uint32_t sA = dbase + stage * STAGE_BYTES;
        const uint32_t sB = sA + 16384;
        #pragma unroll
        for (int j = 0; j < 4; j++) {
            int i = tid + j * 256;
            int row = i >> 3, c16 = i & 7;
            cp_async16(sA + SW128((uint32_t)(row * 128 + c16 * 16)),
                       A + (size_t)(bm + row) * KHL + acol + c16 * 8);
        }
        #pragma unroll
        for (int j = 0; j < 4; j++) {
            int i = tid + j * 256;
            int row = i >> 3, c16 = i & 7;
            cp_async16(sB + SW128((uint32_t)(row * 128 + c16 * 16)),
                       Bt + (size_t)(bn + row) * KBIG + bcol + c16 * 8);
        }
    };

    issue_load(0, 0); CP_COMMIT();
    issue_load(1, 1); CP_COMMIT();

    for (int c = 0; c < NCHUNK; c++) {
        if (c < NCHUNK - 1) { CP_WAIT1(); } else { CP_WAIT0(); }
        __syncthreads();

        const uint32_t sA = dbase + (c & 1) * STAGE_BYTES;
        const uint32_t sB = sA + 16384;

        #pragma unroll
        for (int kk = 0; kk < 4; kk++) {
            uint32_t af[4][4];
            #pragma unroll
            for (int mi = 0; mi < 4; mi++) {
                int row = wm + mi * 16 + (g & 1) * 8 + r;
                int col = kk * 16 + (g >> 1) * 8;
                ldsm_x4(af[mi][0], af[mi][1], af[mi][2], af[mi][3],
                        sA + SW128((uint32_t)(row * 128 + col * 2)));
            }
            uint32_t bf[4][2];
            #pragma unroll
            for (int half = 0; half < 2; half++) {
                int row = wn + half * 16 + (g >> 1) * 8 + r;
                int col = kk * 16 + (g & 1) * 8;
                ldsm_x4(bf[half * 2][0], bf[half * 2][1],
                        bf[half * 2 + 1][0], bf[half * 2 + 1][1],
                        sB + SW128((uint32_t)(row * 128 + col * 2)));
            }
            #pragma unroll
            for (int mi = 0; mi < 4; mi++)
                #pragma unroll
                for (int ni = 0; ni < 4; ni++)
                    mma_bf16(acc[mi][ni], af[mi], bf[ni]);
        }
        __syncthreads();
        if (c + 2 < NCHUNK) { issue_load(c & 1, c + 2); CP_COMMIT(); }
    }
}

// ---------------- phase-1 GEMM: zx = X@W + bias (permuted cols) ----------------
__global__ __launch_bounds__(256) void phase1_kernel(
    const __nv_bfloat16* __restrict__ A,
    const __nv_bfloat16* __restrict__ Bt,
    float* __restrict__ C)
{
    extern __shared__ char dyn[];
    uint32_t dbase = (smem_u32(dyn) + 1023u) & ~1023u;
    const int tid = threadIdx.x;
    const int bm = blockIdx.y * 128;
    const int bn = blockIdx.x * 128;

    float acc[4][4][4];
    #pragma unroll
    for (int i = 0; i < 4; i++)
        #pragma unroll
        for (int j = 0; j < 4; j++)
            #pragma unroll
            for (int k = 0; k < 4; k++)
                acc[i][j][k] = 0.0f;

    gemm_mainloop(A, Bt, dbase, bm, bn, tid, acc);

    const int lane = tid & 31;
    const int wid  = tid >> 5;
    const int wm = (wid >> 2) * 64;
    const int wn = (wid & 3) * 32;
    const int qrow = lane >> 2;
    const int qcol = (lane & 3) * 2;
    #pragma unroll
    for (int mi = 0; mi < 4; mi++) {
        #pragma unroll
        for (int ni = 0; ni < 4; ni++) {
            int row = bm + wm + mi * 16 + qrow;
            int col = bn + wn + ni * 8 + qcol;
            float b0 = g_biasp[col];
            float b1 = g_biasp[col + 1];
            float2 v0 = { acc[mi][ni][0] + b0, acc[mi][ni][1] + b1 };
            float2 v1 = { acc[mi][ni][2] + b0, acc[mi][ni][3] + b1 };
            *reinterpret_cast<float2*>(C + (size_t)row * N4H + col) = v0;
            *reinterpret_cast<float2*>(C + (size_t)(row + 8) * N4H + col) = v1;
        }
    }
}

// ---------------- fused recurrent step: z = h@U; LSTM update in epilogue ------
__global__ __launch_bounds__(256) void fused_step_kernel(
    int t,
    const __nv_bfloat16* __restrict__ hread,
    __nv_bfloat16* __restrict__ hwrite,
    float* __restrict__ out)
{
    extern __shared__ char dyn[];
    uint32_t dbase = (smem_u32(dyn) + 1023u) & ~1023u;
    const int tid = threadIdx.x;
    const int bm = blockIdx.y * 128;
    const int bn = blockIdx.x * 128;

    float acc[4][4][4];
    #pragma unroll
    for (int i = 0; i < 4; i++)
        #pragma unroll
        for (int j = 0; j < 4; j++)
            #pragma unroll
            for (int k = 0; k < 4; k++)
                acc[i][j][k] = 0.0f;

    gemm_mainloop(hread, g_ub, dbase, bm, bn, tid, acc);

    // LSTM epilogue: warp n-tile (32 cols) = 4 gates x 8 k-values.
    const int lane = tid & 31;
    const int wid  = tid >> 5;
    const int wm = (wid >> 2) * 64;
    const int wn = (wid & 3) * 32;
    const int qrow = lane >> 2;
    const int qcol = (lane & 3) * 2;
    const int blk = (bn + wn) >> 5;
    const int colbase = blk * 32 + qcol;   // permuted zx col of gate i
    const int kbase = blk * 8 + qcol;      // real k

    #pragma unroll
    for (int mi = 0; mi < 4; mi++) {
        #pragma unroll
        for (int rr = 0; rr < 2; rr++) {
            const int b = bm + wm + mi * 16 + qrow + rr * 8;
            const size_t zxoff = ((size_t)b * TT + t) * N4H + colbase;
            const float2 zi2 = *reinterpret_cast<const float2*>(g_zx + zxoff);
            const float2 zf2 = *reinterpret_cast<const float2*>(g_zx + zxoff + 8);
            const float2 zg2 = *reinterpret_cast<const float2*>(g_zx + zxoff + 16);
            const float2 zo2 = *reinterpret_cast<const float2*>(g_zx + zxoff + 24);
            const float2 cp2 = *reinterpret_cast<const float2*>(g_c + (size_t)b * 512 + kbase);

            float cn[2], hn[2];
            #pragma unroll
            for (int jj = 0; jj < 2; jj++) {
                const int ai = rr * 2 + jj;
                float zi = acc[mi][0][ai] + (jj ? zi2.y : zi2.x);
                float zf = acc[mi][1][ai] + (jj ? zf2.y : zf2.x);
                float zg = acc[mi][2][ai] + (jj ? zg2.y : zg2.x);
                float zo = acc[mi][3][ai] + (jj ? zo2.y : zo2.x);
                float i_ = sigf(zi);
                float f_ = sigf(zf);
                float g_ = tanh_(zg);
                float o_ = sigf(zo);
                float cpv = jj ? cp2.y : cp2.x;
                cn[jj] = f_ * cpv + i_ * g_;
                hn[jj] = o_ * tanh_(cn[jj]);
            }
            float2 co = { cn[0], cn[1] };
            float2 ho = { hn[0], hn[1] };
            *reinterpret_cast<float2*>(g_c + (size_t)b * 512 + kbase) = co;
            *reinterpret_cast<float2*>(out + ((size_t)b * TT + t) * 512 + kbase) = ho;

            __nv_bfloat16 hi0 = __float2bfloat16(hn[0]);
            __nv_bfloat16 hi1 = __float2bfloat16(hn[1]);
            float lo0 = hn[0] - __bfloat162float(hi0);
            float lo1 = hn[1] - __bfloat162float(hi1);
            __nv_bfloat162 hi2 = __halves2bfloat162(hi0, hi1);
            __nv_bfloat162 lo2 = __floats2bfloat162_rn(lo0, lo1);
            *reinterpret_cast<__nv_bfloat162*>(hwrite + (size_t)b * KHL + kbase) = hi2;
            *reinterpret_cast<__nv_bfloat162*>(hwrite + (size_t)b * KHL + 512 + kbase) = lo2;
        }
    }
}

// ---------------- conversion / init kernels ----------------
__global__ __launch_bounds__(256) void conv_x_kernel(const float* __restrict__ X) {
    int idx = blockIdx.x * 256 + threadIdx.x;          // over 65536*512
    int m = idx >> 9, k = idx & 511;
    float v = X[idx];
    __nv_bfloat16 hi = __float2bfloat16(v);
    g_xhl[(size_t)m * KHL + k] = hi;
    g_xhl[(size_t)m * KHL + 512 + k] = __float2bfloat16(v - __bfloat162float(hi));
}

__global__ __launch_bounds__(256) void conv_w_kernel(const float* __restrict__ W,
                                                     __nv_bfloat16* __restrict__ Bt) {
    int idx = blockIdx.x * 256 + threadIdx.x;          // over 512*2048, W[k][n]
    int k = idx >> 11, n = idx & 2047;
    int gate = n >> 9, kk = n & 511;
    int pn = ((kk >> 3) << 5) + (gate << 3) + (kk & 7);   // gate-interleaved row
    float v = W[idx];
    __nv_bfloat16 hi = __float2bfloat16(v);
    __nv_bfloat16 lo = __float2bfloat16(v - __bfloat162float(hi));
    Bt[(size_t)pn * KBIG + k] = hi;
    Bt[(size_t)pn * KBIG + 512 + k] = lo;
    Bt[(size_t)pn * KBIG + 1024 + k] = hi;
}

__global__ void bias_perm_kernel(const float* __restrict__ bias) {
    int n = blockIdx.x * 256 + threadIdx.x;
    if (n < 2048) {
        int gate = n >> 9, kk = n & 511;
        int pn = ((kk >> 3) << 5) + (gate << 3) + (kk & 7);
        g_biasp[pn] = bias[n];
    }
}

// t = 0 step: h=c=0, gates from zx only
__global__ __launch_bounds__(256) void step0_kernel(float* __restrict__ out,
                                                    __nv_bfloat16* __restrict__ hwrite) {
    int idx = blockIdx.x * 256 + threadIdx.x;          // 0..B*H-1
    int b = idx >> 9;
    int k = idx & 511;
    size_t base = ((size_t)b * TT) * N4H + ((k >> 3) << 5) + (k & 7);
    float zi = g_zx[base];
    float zg = g_zx[base + 16];
    float zo = g_zx[base + 24];
    float i_ = sigf(zi);
    float g_ = tanh_(zg);
    float o_ = sigf(zo);
    float cn = i_ * g_;
    float hn = o_ * tanh_(cn);
    g_c[idx] = cn;
    out[((size_t)b * TT) * 512 + k] = hn;
    __nv_bfloat16 hi = __float2bfloat16(hn);
    hwrite[(size_t)b * KHL + k] = hi;
    hwrite[(size_t)b * KHL + 512 + k] = __float2bfloat16(hn - __bfloat162float(hi));
}

// ---------------- launch ----------------
extern "C" void kernel_launch(void* const* d_in, const int* in_sizes, int n_in,
                              void* d_out, int out_size)
{
    const float* X    = (const float*)d_in[0];
    const float* W    = (const float*)d_in[1];
    const float* U    = (const float*)d_in[2];
    const float* bias = (const float*)d_in[3];
    float* out = (float*)d_out;

    float* zx_p;
    __nv_bfloat16 *xhl_p, *wb_p, *ub_p, *hhl_p;
    cudaGetSymbolAddress((void**)&zx_p,  g_zx);
    cudaGetSymbolAddress((void**)&xhl_p, g_xhl);
    cudaGetSymbolAddress((void**)&wb_p,  g_wb);
    cudaGetSymbolAddress((void**)&ub_p,  g_ub);
    cudaGetSymbolAddress((void**)&hhl_p, g_hhl);

    const int SMEM = 2 * STAGE_BYTES + 1024;   // 66560 -> 2 CTAs/SM
    cudaFuncSetAttribute(phase1_kernel,
                         cudaFuncAttributeMaxDynamicSharedMemorySize, SMEM);
    cudaFuncSetAttribute(fused_step_kernel,
                         cudaFuncAttributeMaxDynamicSharedMemorySize, SMEM);

    // conversions (with gate-interleaved column permutation for W/U/bias)
    conv_x_kernel<<<(65536 * 512) / 256, 256>>>(X);
    conv_w_kernel<<<(512 * 2048) / 256, 256>>>(W, wb_p);
    conv_w_kernel<<<(512 * 2048) / 256, 256>>>(U, ub_p);
    bias_perm_kernel<<<8, 256>>>(bias);

    // Phase 1: zx = X@W + bias  (M=65536, N=2048, permuted cols)
    phase1_kernel<<<dim3(N4H / 128, 65536 / 128), 256, SMEM>>>(xhl_p, wb_p, zx_p);

    // t = 0 (writes h buffer 0)
    step0_kernel<<<(BB * 512) / 256, 256>>>(out, hhl_p);

    // t = 1..63: fused GEMM + LSTM update, double-buffered h
    for (int t = 1; t < TT; t++) {
        const __nv_bfloat16* hread = hhl_p + ((t - 1) & 1) * 1048576;
        __nv_bfloat16* hwrite      = hhl_p + (t & 1) * 1048576;
        fused_step_kernel<<<dim3(N4H / 128, BB / 128), 256, SMEM>>>(t, hread, hwrite, out);
    }
}

// round 10
// speedup vs baseline: 1.0782x; 1.0655x over previous
#include <cuda_runtime.h>
#include <cuda_bf16.h>
#include <cstdint>
#include <math.h>

// Problem dims (fixed)
#define BB 1024
#define TT 64
#define N4H 2048
#define KBIG 1536   // 3*512 split-K
#define KHL  1024   // hi|lo storage per row
#define NCHUNK 24
#define STAGE_BYTES 32768   // 16KB A + 16KB B
#define ZX_STRIDE 132       // floats per row in zx smem (128 + 4 pad)

// ---------------- device scratch ----------------
__device__ float g_zx[134217728];                  // [65536, 2048] X@W + bias (gate-interleaved cols)
__device__ float g_biasp[2048];                    // permuted bias
__device__ __nv_bfloat16 g_xhl[67108864];          // [65536, 1024] hi|lo of X
__device__ __nv_bfloat16 g_wb[3145728];            // [2048, 1536]  W^T split (rows permuted)
__device__ __nv_bfloat16 g_ub[3145728];            // [2048, 1536]  U^T split (rows permuted)
__device__ __nv_bfloat16 g_hhl[2097152];           // 2 x [1024, 1024] hi|lo of h (double buffer)
__device__ unsigned g_gen = 0;                     // grid-barrier generation (monotonic)
__device__ unsigned g_cnt = 0;                     // grid-barrier arrival counter (self-resetting)

// ---------------- helpers ----------------
#define SW128(x) ((x) ^ (((x) >> 3) & 0x70))

__device__ __forceinline__ uint32_t smem_u32(const void* p) {
    uint32_t a;
    asm("{ .reg .u64 t; cvta.to.shared.u64 t, %1; cvt.u32.u64 %0, t; }" : "=r"(a) : "l"(p));
    return a;
}
__device__ __forceinline__ void cp_async16(uint32_t dst, const void* src) {
    asm volatile("cp.async.cg.shared.global [%0], [%1], 16;" :: "r"(dst), "l"(src));
}
#define CP_COMMIT() asm volatile("cp.async.commit_group;" ::: "memory")
#define CP_WAIT1()  asm volatile("cp.async.wait_group 1;" ::: "memory")
#define CP_WAIT0()  asm volatile("cp.async.wait_group 0;" ::: "memory")

__device__ __forceinline__ void ldsm_x4(uint32_t& r0, uint32_t& r1, uint32_t& r2, uint32_t& r3,
                                        uint32_t addr) {
    asm volatile("ldmatrix.sync.aligned.m8n8.x4.shared.b16 {%0,%1,%2,%3}, [%4];"
                 : "=r"(r0), "=r"(r1), "=r"(r2), "=r"(r3) : "r"(addr));
}
__device__ __forceinline__ void mma_bf16(float* c, const uint32_t* a, const uint32_t* b) {
    asm volatile(
        "mma.sync.aligned.m16n8k16.row.col.f32.bf16.bf16.f32 "
        "{%0,%1,%2,%3}, {%4,%5,%6,%7}, {%8,%9}, {%0,%1,%2,%3};"
        : "+f"(c[0]), "+f"(c[1]), "+f"(c[2]), "+f"(c[3])
        : "r"(a[0]), "r"(a[1]), "r"(a[2]), "r"(a[3]), "r"(b[0]), "r"(b[1]));
}

// fast activations (MUFU-based, err ~1e-6)
__device__ __forceinline__ float sigf(float x) {
    return 1.0f / (1.0f + __expf(-x));
}
__device__ __forceinline__ float tanh_(float x) {
    float ax = fabsf(x);
    float e  = __expf(2.0f * ax);
    float r  = 1.0f - 2.0f / (e + 1.0f);
    return copysignf(r, x);
}

// ---------------- grid barrier (all CTAs resident; replay-safe) ----------------
__device__ __forceinline__ void grid_barrier(int tid) {
    __threadfence();                 // publish this thread's stores
    __syncthreads();                 // order all CTA threads' stores before tid0's release
    if (tid == 0) {
        unsigned gen = *((volatile unsigned*)&g_gen);   // safe: can't advance w/o my arrival
        unsigned old = atomicAdd(&g_cnt, 1);
        if (old == 127u) {           // last of 128 CTAs
            atomicExch(&g_cnt, 0u);
            __threadfence();
            atomicAdd(&g_gen, 1u);
        } else {
            while (*((volatile unsigned*)&g_gen) == gen) { }
        }
        __threadfence();
    }
    __syncthreads();
}

// ---------------- shared GEMM mainloop (2-stage) for phase-1 ----------------
__device__ __forceinline__ void gemm_mainloop(
    const __nv_bfloat16* __restrict__ A,
    const __nv_bfloat16* __restrict__ Bt,
    uint32_t dbase, int bm, int bn, int tid,
    float acc[4][4][4])
{
    const int lane = tid & 31;
    const int wid  = tid >> 5;
    const int wm = (wid >> 2) * 64;
    const int wn = (wid & 3) * 32;
    const int g = lane >> 3;
    const int r = lane & 7;

    auto issue_load = [&](int stage, int c) {
        const int seg  = c >> 3;
        const int acol = ((seg == 2) ? 512 : 0) + (c & 7) * 64;
        const int bcol = c * 64;
        const uint32_t sA = dbase + stage * STAGE_BYTES;
        const uint32_t sB = sA + 16384;
        #pragma unroll
        for (int j = 0; j < 4; j++) {
            int i = tid + j * 256;
            int row = i >> 3, c16 = i & 7;
            cp_async16(sA + SW128((uint32_t)(row * 128 + c16 * 16)),
                       A + (size_t)(bm + row) * KHL + acol + c16 * 8);
        }
        #pragma unroll
        for (int j = 0; j < 4; j++) {
            int i = tid + j * 256;
            int row = i >> 3, c16 = i & 7;
            cp_async16(sB + SW128((uint32_t)(row * 128 + c16 * 16)),
                       Bt + (size_t)(bn + row) * KBIG + bcol + c16 * 8);
        }
    };

    issue_load(0, 0); CP_COMMIT();
    issue_load(1, 1); CP_COMMIT();

    for (int c = 0; c < NCHUNK; c++) {
        if (c < NCHUNK - 1) { CP_WAIT1(); } else { CP_WAIT0(); }
        __syncthreads();

        const uint32_t sA = dbase + (c & 1) * STAGE_BYTES;
        const uint32_t sB = sA + 16384;

        #pragma unroll
        for (int kk = 0; kk < 4; kk++) {
            uint32_t af[4][4];
            #pragma unroll
            for (int mi = 0; mi < 4; mi++) {
                int row = wm + mi * 16 + (g & 1) * 8 + r;
                int col = kk * 16 + (g >> 1) * 8;
                ldsm_x4(af[mi][0], af[mi][1], af[mi][2], af[mi][3],
                        sA + SW128((uint32_t)(row * 128 + col * 2)));
            }
            uint32_t bf[4][2];
            #pragma unroll
            for (int half = 0; half < 2; half++) {
                int row = wn + half * 16 + (g >> 1) * 8 + r;
                int col = kk * 16 + (g & 1) * 8;
                ldsm_x4(bf[half * 2][0], bf[half * 2][1],
                        bf[half * 2 + 1][0], bf[half * 2 + 1][1],
                        sB + SW128((uint32_t)(row * 128 + col * 2)));
            }
            #pragma unroll
            for (int mi = 0; mi < 4; mi++)
                #pragma unroll
                for (int ni = 0; ni < 4; ni++)
                    mma_bf16(acc[mi][ni], af[mi], bf[ni]);
        }
        __syncthreads();
        if (c + 2 < NCHUNK) { issue_load(c & 1, c + 2); CP_COMMIT(); }
    }
}

// ---------------- phase-1 GEMM: zx = X@W + bias (permuted cols) ----------------
__global__ __launch_bounds__(256) void phase1_kernel(
    const __nv_bfloat16* __restrict__ A,
    const __nv_bfloat16* __restrict__ Bt,
    float* __restrict__ C)
{
    extern __shared__ char dyn[];
    uint32_t dbase = (smem_u32(dyn) + 1023u) & ~1023u;
    const int tid = threadIdx.x;
    const int bm = blockIdx.y * 128;
    const int bn = blockIdx.x * 128;

    float acc[4][4][4];
    #pragma unroll
    for (int i = 0; i < 4; i++)
        #pragma unroll
        for (int j = 0; j < 4; j++)
            #pragma unroll
            for (int k = 0; k < 4; k++)
                acc[i][j][k] = 0.0f;

    gemm_mainloop(A, Bt, dbase, bm, bn, tid, acc);

    const int lane = tid & 31;
    const int wid  = tid >> 5;
    const int wm = (wid >> 2) * 64;
    const int wn = (wid & 3) * 32;
    const int qrow = lane >> 2;
    const int qcol = (lane & 3) * 2;
    #pragma unroll
    for (int mi = 0; mi < 4; mi++) {
        #pragma unroll
        for (int ni = 0; ni < 4; ni++) {
            int row = bm + wm + mi * 16 + qrow;
            int col = bn + wn + ni * 8 + qcol;
            float b0 = g_biasp[col];
            float b1 = g_biasp[col + 1];
            float2 v0 = { acc[mi][ni][0] + b0, acc[mi][ni][1] + b1 };
            float2 v1 = { acc[mi][ni][2] + b0, acc[mi][ni][3] + b1 };
            *reinterpret_cast<float2*>(C + (size_t)row * N4H + col) = v0;
            *reinterpret_cast<float2*>(C + (size_t)(row + 8) * N4H + col) = v1;
        }
    }
}

// ---------------- persistent LSTM recurrence: all 64 steps in one kernel ------
// grid = (16, 8) = 128 CTAs (all resident). Each CTA owns tile (bm, bn) forever.
// Per step: 2-stage GEMM mainloop (h@U) with zx tile prefetched to SMEM inside
// chunk-1's cp.async group; fused LSTM epilogue (zx from SMEM, c in registers);
// h written hi/lo bf16 to a double buffer; one grid barrier per step.
__global__ __launch_bounds__(256) void lstm_persistent_kernel(
    __nv_bfloat16* __restrict__ hbuf,   // g_hhl base (2 buffers of 1048576)
    float* __restrict__ out)
{
    extern __shared__ char dyn[];
    char* dynp = (char*)((((uintptr_t)dyn) + 1023u) & ~(uintptr_t)1023u);
    const uint32_t dbase = smem_u32(dynp);
    float* zx_s = (float*)(dynp + 2 * STAGE_BYTES);
    const uint32_t zxs_u32 = dbase + 2 * STAGE_BYTES;

    const int tid  = threadIdx.x;
    const int lane = tid & 31;
    const int wid  = tid >> 5;
    const int wm = (wid >> 2) * 64;
    const int wn = (wid & 3) * 32;
    const int g = lane >> 3;
    const int r = lane & 7;
    const int bm = blockIdx.y * 128;
    const int bn = blockIdx.x * 128;
    const int qrow = lane >> 2;
    const int qcol = (lane & 3) * 2;
    const int kbase = ((bn + wn) >> 2) + qcol;    // real k index (tile owns 32 k's)

    float c_reg[4][2][2];
    #pragma unroll
    for (int a = 0; a < 4; a++)
        #pragma unroll
        for (int b = 0; b < 2; b++)
            #pragma unroll
            for (int cc = 0; cc < 2; cc++)
                c_reg[a][b][cc] = 0.0f;

    for (int t = 0; t < TT; t++) {
        if (t > 0) grid_barrier(tid);

        float acc[4][4][4];
        #pragma unroll
        for (int i = 0; i < 4; i++)
            #pragma unroll
            for (int j = 0; j < 4; j++)
                #pragma unroll
                for (int k = 0; k < 4; k++)
                    acc[i][j][k] = 0.0f;

        // zx tile loader: 128 rows x 512B -> smem rows of ZX_STRIDE floats
        auto issue_zx = [&]() {
            #pragma unroll
            for (int j = 0; j < 16; j++) {
                int i = tid + j * 256;
                int row = i >> 5, seg = i & 31;
                cp_async16(zxs_u32 + (uint32_t)(row * ZX_STRIDE * 4 + seg * 16),
                           g_zx + ((size_t)(bm + row) * TT + t) * N4H + bn + seg * 4);
            }
        };

        if (t == 0) {
            issue_zx(); CP_COMMIT(); CP_WAIT0();
            __syncthreads();
        } else {
            const __nv_bfloat16* hread = hbuf + (size_t)((t + 1) & 1) * 1048576;

            auto issue_load = [&](int stage, int c) {
                const int seg  = c >> 3;
                const int acol = ((seg == 2) ? 512 : 0) + (c & 7) * 64;
                const int bcol = c * 64;
                const uint32_t sA = dbase + stage * STAGE_BYTES;
                const uint32_t sB = sA + 16384;
                #pragma unroll
                for (int j = 0; j < 4; j++) {
                    int i = tid + j * 256;
                    int row = i >> 3, c16 = i & 7;
                    cp_async16(sA + SW128((uint32_t)(row * 128 + c16 * 16)),
                               hread + (size_t)(bm + row) * KHL + acol + c16 * 8);
                }
                #pragma unroll
                for (int j = 0; j < 4; j++) {
                    int i = tid + j * 256;
                    int row = i >> 3, c16 = i & 7;
                    cp_async16(sB + SW128((uint32_t)(row * 128 + c16 * 16)),
                               g_ub + (size_t)(bn + row) * KBIG + bcol + c16 * 8);
                }
            };

            issue_load(0, 0); CP_COMMIT();
            issue_load(1, 1); issue_zx(); CP_COMMIT();   // zx rides with chunk 1

            for (int c = 0; c < NCHUNK; c++) {
                if (c < NCHUNK - 1) { CP_WAIT1(); } else { CP_WAIT0(); }
                __syncthreads();

                const uint32_t sA = dbase + (c & 1) * STAGE_BYTES;
                const uint32_t sB = sA + 16384;

                #pragma unroll
                for (int kk = 0; kk < 4; kk++) {
                    uint32_t af[4][4];
                    #pragma unroll
                    for (int mi = 0; mi < 4; mi++) {
                        int row = wm + mi * 16 + (g & 1) * 8 + r;
                        int col = kk * 16 + (g >> 1) * 8;
                        ldsm_x4(af[mi][0], af[mi][1], af[mi][2], af[mi][3],
                                sA + SW128((uint32_t)(row * 128 + col * 2)));
                    }
                    uint32_t bf[4][2];
                    #pragma unroll
                    for (int half = 0; half < 2; half++) {
                        int row = wn + half * 16 + (g >> 1) * 8 + r;
                        int col = kk * 16 + (g & 1) * 8;
                        ldsm_x4(bf[half * 2][0], bf[half * 2][1],
                                bf[half * 2 + 1][0], bf[half * 2 + 1][1],
                                sB + SW128((uint32_t)(row * 128 + col * 2)));
                    }
                    #pragma unroll
                    for (int mi = 0; mi < 4; mi++)
                        #pragma unroll
                        for (int ni = 0; ni < 4; ni++)
                            mma_bf16(acc[mi][ni], af[mi], bf[ni]);
                }
                __syncthreads();
                if (c + 2 < NCHUNK) { issue_load(c & 1, c + 2); CP_COMMIT(); }
            }
        }

        // ---- fused LSTM epilogue (zx from SMEM, c in registers) ----
        __nv_bfloat16* hwrite = hbuf + (size_t)(t & 1) * 1048576;
        #pragma unroll
        for (int mi = 0; mi < 4; mi++) {
            #pragma unroll
            for (int rr = 0; rr < 2; rr++) {
                const int srow = wm + mi * 16 + qrow + rr * 8;
                const int b = bm + srow;
                const float* zrow = zx_s + srow * ZX_STRIDE + wn + qcol;
                const float2 zi2 = *reinterpret_cast<const float2*>(zrow);
                const float2 zf2 = *reinterpret_cast<const float2*>(zrow + 8);
                const float2 zg2 = *reinterpret_cast<const float2*>(zrow + 16);
                const float2 zo2 = *reinterpret_cast<const float2*>(zrow + 24);

                float cn[2], hn[2];
                #pragma unroll
                for (int jj = 0; jj < 2; jj++) {
                    const int ai = rr * 2 + jj;
                    float zi = acc[mi][0][ai] + (jj ? zi2.y : zi2.x);
                    float zf = acc[mi][1][ai] + (jj ? zf2.y : zf2.x);
                    float zg = acc[mi][2][ai] + (jj ? zg2.y : zg2.x);
                    float zo = acc[mi][3][ai] + (jj ? zo2.y : zo2.x);
                    float i_ = sigf(zi);
                    float f_ = sigf(zf);
                    float g_ = tanh_(zg);
                    float o_ = sigf(zo);
                    cn[jj] = f_ * c_reg[mi][rr][jj] + i_ * g_;
                    hn[jj] = o_ * tanh_(cn[jj]);
                    c_reg[mi][rr][jj] = cn[jj];
                }
                float2 ho = { hn[0], hn[1] };
                *reinterpret_cast<float2*>(out + ((size_t)b * TT + t) * 512 + kbase) = ho;

                __nv_bfloat16 hi0 = __float2bfloat16(hn[0]);
                __nv_bfloat16 hi1 = __float2bfloat16(hn[1]);
                float lo0 = hn[0] - __bfloat162float(hi0);
                float lo1 = hn[1] - __bfloat162float(hi1);
                __nv_bfloat162 hi2 = __halves2bfloat162(hi0, hi1);
                __nv_bfloat162 lo2 = __floats2bfloat162_rn(lo0, lo1);
                *reinterpret_cast<__nv_bfloat162*>(hwrite + (size_t)b * KHL + kbase) = hi2;
                *reinterpret_cast<__nv_bfloat162*>(hwrite + (size_t)b * KHL + 512 + kbase) = lo2;
            }
        }
    }
}

// ---------------- conversion / init kernels ----------------
__global__ __launch_bounds__(256) void conv_x_kernel(const float* __restrict__ X) {
    int idx = blockIdx.x * 256 + threadIdx.x;          // over 65536*512
    int m = idx >> 9, k = idx & 511;
    float v = X[idx];
    __nv_bfloat16 hi = __float2bfloat16(v);
    g_xhl[(size_t)m * KHL + k] = hi;
    g_xhl[(size_t)m * KHL + 512 + k] = __float2bfloat16(v - __bfloat162float(hi));
}

__global__ __launch_bounds__(256) void conv_w_kernel(const float* __restrict__ W,
                                                     __nv_bfloat16* __restrict__ Bt) {
    int idx = blockIdx.x * 256 + threadIdx.x;          // over 512*2048, W[k][n]
    int k = idx >> 11, n = idx & 2047;
    int gate = n >> 9, kk = n & 511;
    int pn = ((kk >> 3) << 5) + (gate << 3) + (kk & 7);   // gate-interleaved row
    float v = W[idx];
    __nv_bfloat16 hi = __float2bfloat16(v);
    __nv_bfloat16 lo = __float2bfloat16(v - __bfloat162float(hi));
    Bt[(size_t)pn * KBIG + k] = hi;
    Bt[(size_t)pn * KBIG + 512 + k] = lo;
    Bt[(size_t)pn * KBIG + 1024 + k] = hi;
}

__global__ void bias_perm_kernel(const float* __restrict__ bias) {
    int n = blockIdx.x * 256 + threadIdx.x;
    if (n < 2048) {
        int gate = n >> 9, kk = n & 511;
        int pn = ((kk >> 3) << 5) + (gate << 3) + (kk & 7);
        g_biasp[pn] = bias[n];
    }
}

// ---------------- launch ----------------
extern "C" void kernel_launch(void* const* d_in, const int* in_sizes, int n_in,
                              void* d_out, int out_size)
{
    const float* X    = (const float*)d_in[0];
    const float* W    = (const float*)d_in[1];
    const float* U    = (const float*)d_in[2];
    const float* bias = (const float*)d_in[3];
    float* out = (float*)d_out;

    float* zx_p;
    __nv_bfloat16 *xhl_p, *wb_p, *ub_p, *hhl_p;
    cudaGetSymbolAddress((void**)&zx_p,  g_zx);
    cudaGetSymbolAddress((void**)&xhl_p, g_xhl);
    cudaGetSymbolAddress((void**)&wb_p,  g_wb);
    cudaGetSymbolAddress((void**)&ub_p,  g_ub);
    cudaGetSymbolAddress((void**)&hhl_p, g_hhl);

    const int SMEM_P1 = 2 * STAGE_BYTES + 1024;                    // 66560 -> 2 CTAs/SM
    const int SMEM_RC = 2 * STAGE_BYTES + 128 * ZX_STRIDE * 4 + 1024;  // 134144
    cudaFuncSetAttribute(phase1_kernel,
                         cudaFuncAttributeMaxDynamicSharedMemorySize, SMEM_P1);
    cudaFuncSetAttribute(lstm_persistent_kernel,
                         cudaFuncAttributeMaxDynamicSharedMemorySize, SMEM_RC);

    // conversions (gate-interleaved permutation for W/U/bias)
    conv_x_kernel<<<(65536 * 512) / 256, 256>>>(X);
    conv_w_kernel<<<(512 * 2048) / 256, 256>>>(W, wb_p);
    conv_w_kernel<<<(512 * 2048) / 256, 256>>>(U, ub_p);
    bias_perm_kernel<<<8, 256>>>(bias);

    // Phase 1: zx = X@W + bias  (M=65536, N=2048, permuted cols)
    phase1_kernel<<<dim3(N4H / 128, 65536 / 128), 256, SMEM_P1>>>(xhl_p, wb_p, zx_p);

    // Persistent recurrence: all 64 steps, 128 resident CTAs, grid barriers
    lstm_persistent_kernel<<<dim3(16, 8), 256, SMEM_RC>>>(hhl_p, out);
}